// round 1
// baseline (speedup 1.0000x reference)
#include <cuda_runtime.h>
#include <cstdint>
#include <math.h>

// Problem constants
#define B_   16
#define C_   256
#define H_   32
#define W_   32
#define HW_  1024
#define N_   16384      // B*H*W
#define K_   8192
#define NC_  4194304    // N_*C_ (total z elements)

// Output layout (flattened concat of reference return tuple, fp32)
#define OFF_Q    0
#define OFF_IDX  4194304
#define OFF_P    4210688
#define OFF_LVQ  4210689
#define OFF_LC   4210690

// GEMM tiling
#define TILE_N    64
#define TILE_K    128
#define AS_STRIDE 68     // [256][68] padded, row 272B (16B aligned)
#define BS_STRIDE 132    // [64][132] padded, row 528B (16B aligned)
#define SMEM_FLOATS (256 * AS_STRIDE + 64 * BS_STRIDE)
#define SMEM_BYTES  (SMEM_FLOATS * 4)   // 103424 B

// Scratch (no allocations allowed)
__device__ int   g_counts[K_];
__device__ int   g_indices[N_];
__device__ float g_cn2[K_];
__device__ float g_partials[512];

// ---------------------------------------------------------------------------
// Zero counts
// ---------------------------------------------------------------------------
__global__ void zero_kernel() {
    int i = blockIdx.x * blockDim.x + threadIdx.x;
    if (i < K_) g_counts[i] = 0;
}

// ---------------------------------------------------------------------------
// Codebook row norms: one warp per row
// ---------------------------------------------------------------------------
__global__ void __launch_bounds__(256) cn2_kernel(const float* __restrict__ cb) {
    int warp = (blockIdx.x * blockDim.x + threadIdx.x) >> 5;
    int lane = threadIdx.x & 31;
    if (warp >= K_) return;
    const float4* row = (const float4*)(cb + (size_t)warp * C_);
    float s = 0.f;
#pragma unroll
    for (int i = 0; i < 2; ++i) {
        float4 v = row[lane + i * 32];
        s += v.x * v.x + v.y * v.y + v.z * v.z + v.w * v.w;
    }
#pragma unroll
    for (int o = 16; o; o >>= 1) s += __shfl_xor_sync(0xFFFFFFFFu, s, o);
    if (lane == 0) g_cn2[warp] = s;
}

// ---------------------------------------------------------------------------
// Fused distance GEMM + argmin.
// Grid: N_/TILE_N = 256 CTAs. Block: 128 threads, 8x8 register tile.
// SMEM: full z-tile As[256][68] (resident), codebook chunk Bs[64][132].
// dist = ||e||^2 - 2 z.e  (row-constant ||z||^2 dropped; argmin invariant)
// ---------------------------------------------------------------------------
__global__ void __launch_bounds__(128) argmin_kernel(const float* __restrict__ z,
                                                     const float* __restrict__ cb,
                                                     float* __restrict__ out_idx_f) {
    extern __shared__ float sm[];
    float* As = sm;                      // [256][AS_STRIDE] layout [c][n]
    float* Bs = sm + 256 * AS_STRIDE;    // [64][BS_STRIDE]  layout [cc][k]

    const int tid = threadIdx.x;
    const int tx = tid & 15;             // k-direction (16 x 8 = 128)
    const int ty = tid >> 4;             // n-direction (8 x 8 = 64)

    const int n0 = blockIdx.x * TILE_N;
    const int b  = n0 >> 10;             // HW_=1024, TILE_N divides it
    const int hw0 = n0 & 1023;
    const float* zb = z + (size_t)b * C_ * HW_ + hw0;

    // Load full z tile: As[c][n] = z[b, c, hw0+n]  (coalesced over n)
    {
        const int n = tid & 63;
        for (int c = (tid >> 6); c < C_; c += 2)
            As[c * AS_STRIDE + n] = zb[(size_t)c * HW_ + n];
    }

    float rmin[8];
    int   ridx[8];
#pragma unroll
    for (int i = 0; i < 8; ++i) { rmin[i] = 3.4e38f; ridx[i] = 0; }

    for (int kt = 0; kt < K_; kt += TILE_K) {
        float acc[8][8];
#pragma unroll
        for (int i = 0; i < 8; ++i)
#pragma unroll
            for (int j = 0; j < 8; ++j) acc[i][j] = 0.f;

        for (int ch = 0; ch < 4; ++ch) {
            __syncthreads();   // previous compute done before Bs overwrite (also orders As load)
            {
                const int cc = tid & 63;
                const int kb = tid >> 6;
                const float* cbp = cb + (size_t)(kt + kb) * C_ + ch * 64 + cc;
                for (int k = kb; k < TILE_K; k += 2, cbp += 2 * C_)
                    Bs[cc * BS_STRIDE + k] = *cbp;
            }
            __syncthreads();

            const float* aptr = As + (ch * 64) * AS_STRIDE + ty * 8;
            const float* bptr = Bs + tx * 8;
#pragma unroll 4
            for (int cc = 0; cc < 64; ++cc) {
                float4 a0 = *(const float4*)(aptr);
                float4 a1 = *(const float4*)(aptr + 4);
                float4 b0 = *(const float4*)(bptr);
                float4 b1 = *(const float4*)(bptr + 4);
                aptr += AS_STRIDE; bptr += BS_STRIDE;
                float av[8] = {a0.x, a0.y, a0.z, a0.w, a1.x, a1.y, a1.z, a1.w};
                float bv[8] = {b0.x, b0.y, b0.z, b0.w, b1.x, b1.y, b1.z, b1.w};
#pragma unroll
                for (int i = 0; i < 8; ++i)
#pragma unroll
                    for (int j = 0; j < 8; ++j)
                        acc[i][j] = fmaf(av[i], bv[j], acc[i][j]);
            }
        }

        // epilogue: running argmin (j ascending = k ascending, strict < keeps first)
#pragma unroll
        for (int j = 0; j < 8; ++j) {
            const int k = kt + tx * 8 + j;
            const float c2 = g_cn2[k];
#pragma unroll
            for (int i = 0; i < 8; ++i) {
                float d = fmaf(-2.f, acc[i][j], c2);
                if (d < rmin[i]) { rmin[i] = d; ridx[i] = k; }
            }
        }
    }

    // Cross-tx reduction via SMEM (tie -> lower index, matching jnp.argmin)
    __syncthreads();
    float* vals = sm;                       // [64][16]
    int*   idxs = (int*)(sm + 64 * 16);     // [64][16]
#pragma unroll
    for (int i = 0; i < 8; ++i) {
        vals[(ty * 8 + i) * 16 + tx] = rmin[i];
        idxs[(ty * 8 + i) * 16 + tx] = ridx[i];
    }
    __syncthreads();
    if (tid < TILE_N) {
        float bv = vals[tid * 16];
        int   bi = idxs[tid * 16];
        for (int t = 1; t < 16; ++t) {
            float v = vals[tid * 16 + t];
            int   ii = idxs[tid * 16 + t];
            if (v < bv || (v == bv && ii < bi)) { bv = v; bi = ii; }
        }
        int n = n0 + tid;
        g_indices[n] = bi;
        out_idx_f[n] = (float)bi;
    }
}

// ---------------------------------------------------------------------------
// Gather quantized output (coalesced [B,C,H,W] writes via SMEM transpose),
// per-block squared-error partial sums, codebook usage counts.
// Grid: B_*H_ = 512 blocks, 256 threads. Block handles one (b,h): 32 points.
// ---------------------------------------------------------------------------
__global__ void __launch_bounds__(256) gather_kernel(const float* __restrict__ z,
                                                     const float* __restrict__ cb,
                                                     float* __restrict__ out_q) {
    __shared__ float q[32][257];
    __shared__ int   sidx[32];
    __shared__ float red[256];
    const int t = threadIdx.x;
    const int b = blockIdx.x >> 5;
    const int h = blockIdx.x & 31;
    const int nbase = b * HW_ + h * W_;

    if (t < 32) {
        int idx = g_indices[nbase + t];
        sidx[t] = idx;
        atomicAdd(&g_counts[idx], 1);   // integer atomics: deterministic
    }
    __syncthreads();

    for (int w = 0; w < 32; ++w)
        q[w][t] = cb[(size_t)sidx[w] * C_ + t];   // coalesced row loads
    __syncthreads();

    float lsum = 0.f;
    const int w  = t & 31;
    const int cg = t >> 5;   // 8 c-groups
    const size_t base = (size_t)b * C_ * HW_ + h * W_ + w;
    for (int c = cg; c < C_; c += 8) {
        const size_t o = base + (size_t)c * HW_;
        float qv = q[w][c];
        float zv = z[o];
        out_q[o] = qv;                   // 32 consecutive w -> 128B coalesced
        float dd = zv - qv;
        lsum = fmaf(dd, dd, lsum);
    }

    red[t] = lsum;
    __syncthreads();
    for (int s = 128; s > 0; s >>= 1) {
        if (t < s) red[t] += red[t + s];
        __syncthreads();
    }
    if (t == 0) g_partials[blockIdx.x] = red[0];
}

// ---------------------------------------------------------------------------
// Finalize: losses (deterministic ordered reduction) + perplexity
// ---------------------------------------------------------------------------
__global__ void __launch_bounds__(256) finalize_kernel(float* __restrict__ out) {
    __shared__ float red[256];
    const int t = threadIdx.x;

    float s = 0.f;
    for (int i = t; i < 512; i += 256) s += g_partials[i];
    red[t] = s;
    __syncthreads();
    for (int st = 128; st > 0; st >>= 1) {
        if (t < st) red[t] += red[t + st];
        __syncthreads();
    }
    if (t == 0) {
        float loss = red[0] / (float)NC_;
        out[OFF_LVQ] = loss;
        out[OFF_LC]  = loss;
    }
    __syncthreads();

    float e = 0.f;
    for (int k = t; k < K_; k += 256) {
        float p = (float)g_counts[k] * (1.f / (float)N_);
        if (p > 0.f) e += p * logf(p);    // p >= 1/N >> 1e-10 clip
    }
    red[t] = e;
    __syncthreads();
    for (int st = 128; st > 0; st >>= 1) {
        if (t < st) red[t] += red[t + st];
        __syncthreads();
    }
    if (t == 0) out[OFF_P] = expf(-red[0]);
}

// ---------------------------------------------------------------------------
extern "C" void kernel_launch(void* const* d_in, const int* in_sizes, int n_in,
                              void* d_out, int out_size) {
    const float* z  = (const float*)d_in[0];
    const float* cb = (const float*)d_in[1];
    float* out = (float*)d_out;

    cudaFuncSetAttribute(argmin_kernel,
                         cudaFuncAttributeMaxDynamicSharedMemorySize, SMEM_BYTES);

    zero_kernel<<<(K_ + 255) / 256, 256>>>();
    cn2_kernel<<<(K_ * 32) / 256, 256>>>(cb);
    argmin_kernel<<<N_ / TILE_N, 128, SMEM_BYTES>>>(z, cb, out + OFF_IDX);
    gather_kernel<<<B_ * H_, 256>>>(z, cb, out + OFF_Q);
    finalize_kernel<<<1, 256>>>(out);
}

// round 5
// speedup vs baseline: 1.1906x; 1.1906x over previous
#include <cuda_runtime.h>
#include <cstdint>
#include <math.h>
#include <float.h>

// Problem constants
#define B_   16
#define C_   256
#define HW_  1024
#define N_   16384
#define K_   8192
#define NC_  4194304

// Output layout
#define OFF_Q    0
#define OFF_IDX  4194304
#define OFF_P    4210688
#define OFF_LVQ  4210689
#define OFF_LC   4210690

#define NBLOCKS   128    // N_/128
#define QBLOCKS   64     // K_/128
#define NG        512    // QBLOCKS*8
#define STAGE_BYTES 65536
#define SMEM_MAIN   131072
#define MARGIN    2e-2f

// Scratch: fragment-ordered tf32 hi/lo operands
__device__ float4 g_Ah[NBLOCKS * 8 * 1024];
__device__ float4 g_Al[NBLOCKS * 8 * 1024];
__device__ float2 g_Bh[QBLOCKS * 8 * 2048];
__device__ float2 g_Bl[QBLOCKS * 8 * 2048];
__device__ float  g_cn2[K_];
__device__ int    g_counts[K_];
__device__ int    g_indices[N_];
__device__ int    g_flag[N_];
__device__ float  g_partials[512];

// ---------------------------------------------------------------------------
__device__ __forceinline__ uint32_t smem_u32(const void* p) {
    uint32_t a;
    asm("{ .reg .u64 t; cvta.to.shared.u64 t, %1; cvt.u32.u64 %0, t; }" : "=r"(a) : "l"(p));
    return a;
}
__device__ __forceinline__ float tf32_rn(float x) {
    float r; asm("cvt.rna.tf32.f32 %0, %1;" : "=f"(r) : "f"(x)); return r;
}
__device__ __forceinline__ void cp16(uint32_t dst, const void* src) {
    asm volatile("cp.async.cg.shared.global [%0], [%1], 16;" :: "r"(dst), "l"(src));
}
#define CP_COMMIT() asm volatile("cp.async.commit_group;" ::: "memory")

__device__ __forceinline__ void mma_tf32(float* c, uint4 a, uint2 b) {
    asm("mma.sync.aligned.m16n8k8.row.col.f32.tf32.tf32.f32 "
        "{%0,%1,%2,%3}, {%4,%5,%6,%7}, {%8,%9}, {%0,%1,%2,%3};"
        : "+f"(c[0]), "+f"(c[1]), "+f"(c[2]), "+f"(c[3])
        : "r"(a.x), "r"(a.y), "r"(a.z), "r"(a.w), "r"(b.x), "r"(b.y));
}

// ---------------------------------------------------------------------------
__global__ void zero_kernel() {
    int i = blockIdx.x * blockDim.x + threadIdx.x;
    if (i < K_) g_counts[i] = 0;
}

__global__ void __launch_bounds__(256) cn2_kernel(const float* __restrict__ cb) {
    int warp = (blockIdx.x * blockDim.x + threadIdx.x) >> 5;
    int lane = threadIdx.x & 31;
    if (warp >= K_) return;
    const float4* row = (const float4*)(cb + (size_t)warp * C_);
    float s = 0.f;
#pragma unroll
    for (int i = 0; i < 2; ++i) {
        float4 v = row[lane + i * 32];
        s += v.x * v.x + v.y * v.y + v.z * v.z + v.w * v.w;
    }
#pragma unroll
    for (int o = 16; o; o >>= 1) s += __shfl_xor_sync(0xFFFFFFFFu, s, o);
    if (lane == 0) g_cn2[warp] = s;
}

// z -> A fragments (transpose + tf32 hi/lo split). Grid 128 blocks x 256 thr.
__global__ void __launch_bounds__(256) splitA_kernel(const float* __restrict__ z) {
    __shared__ float s[32][132];
    const int blk = blockIdx.x;
    const int tid = threadIdx.x;
    const int b = blk >> 3;
    const int hw0 = (blk & 7) * 128;

    for (int ch = 0; ch < 8; ++ch) {
        __syncthreads();
        for (int idx = tid; idx < 4096; idx += 256) {
            int cl = idx >> 7, nl = idx & 127;
            s[cl][nl] = z[((size_t)(b * C_ + ch * 32 + cl)) * HW_ + hw0 + nl];
        }
        __syncthreads();
#pragma unroll
        for (int r = 0; r < 4; ++r) {
            int o4 = tid + r * 256;
            int lane = o4 & 31, kst = (o4 >> 5) & 3, mi = (o4 >> 7) & 3, wm = o4 >> 9;
            int col = lane & 3, row = lane >> 2;
            int m = wm * 64 + mi * 16 + row;
            int c = kst * 8 + col;
            float v0 = s[c][m], v1 = s[c][m + 8], v2 = s[c + 4][m], v3 = s[c + 4][m + 8];
            float4 h, l;
            h.x = tf32_rn(v0); l.x = tf32_rn(v0 - h.x);
            h.y = tf32_rn(v1); l.y = tf32_rn(v1 - h.y);
            h.z = tf32_rn(v2); l.z = tf32_rn(v2 - h.z);
            h.w = tf32_rn(v3); l.w = tf32_rn(v3 - h.w);
            int o = (blk * 8 + ch) * 1024 + o4;
            g_Ah[o] = h;
            g_Al[o] = l;
        }
    }
}

// codebook -> B fragments. Grid 64 qblocks x 256 thr.
__global__ void __launch_bounds__(256) splitB_kernel(const float* __restrict__ cb) {
    const int blk = blockIdx.x;
    const int tid = threadIdx.x;
    for (int ch = 0; ch < 8; ++ch) {
#pragma unroll
        for (int r = 0; r < 8; ++r) {
            int o2 = tid + r * 256;
            int lane = o2 & 31, kst = (o2 >> 5) & 3, ni = (o2 >> 7) & 3, wn = o2 >> 9;
            int q = blk * 128 + wn * 32 + ni * 8 + (lane >> 2);
            int c = ch * 32 + kst * 8 + (lane & 3);
            float v0 = cb[(size_t)q * C_ + c];
            float v1 = cb[(size_t)q * C_ + c + 4];
            float2 h, l;
            h.x = tf32_rn(v0); l.x = tf32_rn(v0 - h.x);
            h.y = tf32_rn(v1); l.y = tf32_rn(v1 - h.y);
            int o = (blk * 8 + ch) * 2048 + o2;
            g_Bh[o] = h;
            g_Bl[o] = l;
        }
    }
}

// ---------------------------------------------------------------------------
// Main: 3-term split-TF32 mma.sync GEMM + argmin screening (top1 idx + top2 val).
// 128 CTAs x 256 thr (8 warps: wm in {0,1}, wn in {0..3}), warp tile 64x32.
// ---------------------------------------------------------------------------
__global__ void __launch_bounds__(256, 1)
mma_argmin_kernel(float* __restrict__ out_idx_f) {
    extern __shared__ char sm[];
    const uint32_t smb = smem_u32(sm);

    const int tid = threadIdx.x;
    const int lane = tid & 31;
    const int w = tid >> 5;
    const int wm = w >> 2, wn = w & 3;
    const int blk = blockIdx.x;

    auto load_stage = [&](int g) {
        const int p = g & 1;
        const int ch = g & 7, qb = g >> 3;
        const uint32_t st = smb + (uint32_t)p * STAGE_BYTES;
        const float4* pAh = g_Ah + (blk * 8 + ch) * 1024;
        const float4* pAl = g_Al + (blk * 8 + ch) * 1024;
        const float2* pBh = g_Bh + (qb * 8 + ch) * 2048;
        const float2* pBl = g_Bl + (qb * 8 + ch) * 2048;
#pragma unroll
        for (int r = 0; r < 4; ++r) {
            int i = tid + r * 256;
            cp16(st + i * 16,              pAh + i);
            cp16(st + 16384 + i * 16,      pAl + i);
            cp16(st + 32768 + i * 16,      (const char*)pBh + i * 16);
            cp16(st + 49152 + i * 16,      (const char*)pBl + i * 16);
        }
        CP_COMMIT();
    };

    load_stage(0);
    load_stage(1);

    float rmin[8], rmin2[8];
    int   ridx[8];
#pragma unroll
    for (int s = 0; s < 8; ++s) { rmin[s] = 3.4e38f; rmin2[s] = 3.4e38f; ridx[s] = 0; }

    const uint32_t aBase = (uint32_t)((wm * 16) * 32 + lane);
    const uint32_t bBase = (uint32_t)((wn * 16) * 32 + lane);

    for (int qb = 0; qb < QBLOCKS; ++qb) {
        float acc[4][4][4];
#pragma unroll
        for (int mi = 0; mi < 4; ++mi)
#pragma unroll
            for (int ni = 0; ni < 4; ++ni)
#pragma unroll
                for (int v = 0; v < 4; ++v) acc[mi][ni][v] = 0.f;

        for (int ch = 0; ch < 8; ++ch) {
            const int g = qb * 8 + ch;
            const int p = g & 1;
            if (g >= NG - 2) asm volatile("cp.async.wait_group 0;" ::: "memory");
            else             asm volatile("cp.async.wait_group 1;" ::: "memory");
            __syncthreads();

            const uint4* sAh = (const uint4*)(sm + (size_t)p * STAGE_BYTES);
            const uint4* sAl = (const uint4*)(sm + (size_t)p * STAGE_BYTES + 16384);
            const uint2* sBh = (const uint2*)(sm + (size_t)p * STAGE_BYTES + 32768);
            const uint2* sBl = (const uint2*)(sm + (size_t)p * STAGE_BYTES + 49152);

#pragma unroll
            for (int kst = 0; kst < 4; ++kst) {
                uint4 ah[4], al[4];
                uint2 bh[4], bl[4];
#pragma unroll
                for (int mi = 0; mi < 4; ++mi) {
                    ah[mi] = sAh[aBase + (mi * 4 + kst) * 32];
                    al[mi] = sAl[aBase + (mi * 4 + kst) * 32];
                }
#pragma unroll
                for (int ni = 0; ni < 4; ++ni) {
                    bh[ni] = sBh[bBase + (ni * 4 + kst) * 32];
                    bl[ni] = sBl[bBase + (ni * 4 + kst) * 32];
                }
#pragma unroll
                for (int mi = 0; mi < 4; ++mi)
#pragma unroll
                    for (int ni = 0; ni < 4; ++ni) {
                        mma_tf32(acc[mi][ni], ah[mi], bh[ni]);
                        mma_tf32(acc[mi][ni], ah[mi], bl[ni]);
                        mma_tf32(acc[mi][ni], al[mi], bh[ni]);
                    }
            }

            __syncthreads();
            if (g < NG - 2) load_stage(g + 2);
        }

        // screening epilogue: top-1 (value+idx) and top-2 (value) per m-slot
#pragma unroll
        for (int ni = 0; ni < 4; ++ni) {
            const int q0 = qb * 128 + wn * 32 + ni * 8 + (lane & 3) * 2;
            const float c2a = __ldg(g_cn2 + q0);
            const float c2b = __ldg(g_cn2 + q0 + 1);
#pragma unroll
            for (int mi = 0; mi < 4; ++mi) {
                float d0 = fmaf(-2.f, acc[mi][ni][0], c2a);
                float d1 = fmaf(-2.f, acc[mi][ni][1], c2b);
                float d2 = fmaf(-2.f, acc[mi][ni][2], c2a);
                float d3 = fmaf(-2.f, acc[mi][ni][3], c2b);
                const int lo = mi * 2, hi = mi * 2 + 1;
                if (d0 < rmin[lo]) { rmin2[lo] = rmin[lo]; rmin[lo] = d0; ridx[lo] = q0; }
                else if (d0 < rmin2[lo]) rmin2[lo] = d0;
                if (d1 < rmin[lo]) { rmin2[lo] = rmin[lo]; rmin[lo] = d1; ridx[lo] = q0 + 1; }
                else if (d1 < rmin2[lo]) rmin2[lo] = d1;
                if (d2 < rmin[hi]) { rmin2[hi] = rmin[hi]; rmin[hi] = d2; ridx[hi] = q0; }
                else if (d2 < rmin2[hi]) rmin2[hi] = d2;
                if (d3 < rmin[hi]) { rmin2[hi] = rmin[hi]; rmin[hi] = d3; ridx[hi] = q0 + 1; }
                else if (d3 < rmin2[hi]) rmin2[hi] = d3;
            }
        }
    }

    // Final cross-thread (v1,i1,v2) reduction; tie -> lower index
    __syncthreads();
    float* rv  = (float*)sm;             // [128][4]
    int*   riv = (int*)(sm + 2048);      // [128][4]
    float* rv2 = (float*)(sm + 4096);    // [128][4]
#pragma unroll
    for (int s = 0; s < 8; ++s) {
        float v1 = rmin[s], v2 = rmin2[s];
        int  i1 = ridx[s];
#pragma unroll
        for (int off = 1; off <= 2; off <<= 1) {
            float ov1 = __shfl_xor_sync(0xFFFFFFFFu, v1, off);
            float ov2 = __shfl_xor_sync(0xFFFFFFFFu, v2, off);
            int  oi1 = __shfl_xor_sync(0xFFFFFFFFu, i1, off);
            if (ov1 < v1 || (ov1 == v1 && oi1 < i1)) {
                v2 = fminf(v1, ov2); v1 = ov1; i1 = oi1;
            } else {
                v2 = fminf(ov1, v2);
            }
        }
        if ((lane & 3) == 0) {
            int row = wm * 64 + (s >> 1) * 16 + (lane >> 2) + (s & 1) * 8;
            rv[row * 4 + wn] = v1;
            riv[row * 4 + wn] = i1;
            rv2[row * 4 + wn] = v2;
        }
    }
    __syncthreads();
    if (tid < 128) {
        float v1 = rv[tid * 4];
        int   i1 = riv[tid * 4];
        float v2 = rv2[tid * 4];
#pragma unroll
        for (int t = 1; t < 4; ++t) {
            float ov1 = rv[tid * 4 + t];
            int  oi1 = riv[tid * 4 + t];
            float ov2 = rv2[tid * 4 + t];
            if (ov1 < v1 || (ov1 == v1 && oi1 < i1)) {
                v2 = fminf(v1, ov2); v1 = ov1; i1 = oi1;
            } else {
                v2 = fminf(ov1, v2);
            }
        }
        const int n = blk * 128 + tid;
        g_flag[n] = (v2 - v1 < MARGIN) ? 1 : 0;
        g_indices[n] = i1;
        out_idx_f[n] = (float)i1;
    }
}

// ---------------------------------------------------------------------------
// Rescue: for flagged points, recompute all 8192 distances with reference
// semantics: d = fl(fl(zn2 + cn2[k]) - 2*dot_f32), argmin tie->lowest index.
// One block per point; non-flagged blocks exit immediately.
// ---------------------------------------------------------------------------
__global__ void __launch_bounds__(256) rescue_kernel(const float* __restrict__ z,
                                                     const float* __restrict__ cb,
                                                     float* __restrict__ out_idx_f) {
    const int n = blockIdx.x;
    if (g_flag[n] == 0) return;

    __shared__ float zrow[256];
    __shared__ float bd[256];
    __shared__ int   bk[256];
    const int t = threadIdx.x;
    const int b = n >> 10, hw = n & 1023;
    zrow[t] = z[((size_t)(b * C_ + t)) * HW_ + hw];
    __syncthreads();

    // zn2 in fp64 -> correctly-rounded fp32 (each thread computes; deterministic)
    double zn2d = 0.0;
    for (int c = 0; c < 256; ++c) zn2d += (double)zrow[c] * (double)zrow[c];
    const float zn2 = (float)zn2d;

    const float4* zr4 = (const float4*)zrow;
    float bestd = FLT_MAX;
    int   bestk = 0x7FFFFFFF;
    for (int k = t; k < K_; k += 256) {
        const float4* cr4 = (const float4*)(cb + (size_t)k * C_);
        float a0 = 0.f, a1 = 0.f, a2 = 0.f, a3 = 0.f;
        float b0 = 0.f, b1 = 0.f, b2 = 0.f, b3 = 0.f;
#pragma unroll
        for (int j = 0; j < 64; j += 2) {
            float4 x = cr4[j],     y = zr4[j];
            a0 = fmaf(x.x, y.x, a0); a1 = fmaf(x.y, y.y, a1);
            a2 = fmaf(x.z, y.z, a2); a3 = fmaf(x.w, y.w, a3);
            float4 x2 = cr4[j + 1], y2 = zr4[j + 1];
            b0 = fmaf(x2.x, y2.x, b0); b1 = fmaf(x2.y, y2.y, b1);
            b2 = fmaf(x2.z, y2.z, b2); b3 = fmaf(x2.w, y2.w, b3);
        }
        float dotf = __fadd_rn(__fadd_rn(__fadd_rn(a0, a1), __fadd_rn(a2, a3)),
                               __fadd_rn(__fadd_rn(b0, b1), __fadd_rn(b2, b3)));
        // reference op order: (zn2 + cn2[k]) - 2*dot, each step fp32-rounded
        float d = __fsub_rn(__fadd_rn(zn2, __ldg(g_cn2 + k)), 2.0f * dotf);
        if (d < bestd || (d == bestd && k < bestk)) { bestd = d; bestk = k; }
    }
    bd[t] = bestd;
    bk[t] = bestk;
    __syncthreads();
    if (t == 0) {
        float v = bd[0]; int ix = bk[0];
        for (int i = 1; i < 256; ++i) {
            if (bd[i] < v || (bd[i] == v && bk[i] < ix)) { v = bd[i]; ix = bk[i]; }
        }
        g_indices[n] = ix;
        out_idx_f[n] = (float)ix;
    }
}

// ---------------------------------------------------------------------------
__global__ void __launch_bounds__(256) gather_kernel(const float* __restrict__ z,
                                                     const float* __restrict__ cb,
                                                     float* __restrict__ out_q) {
    __shared__ float q[32][257];
    __shared__ int   sidx[32];
    __shared__ float red[256];
    const int t = threadIdx.x;
    const int b = blockIdx.x >> 5;
    const int h = blockIdx.x & 31;
    const int nbase = b * HW_ + h * 32;

    if (t < 32) {
        int idx = g_indices[nbase + t];
        sidx[t] = idx;
        atomicAdd(&g_counts[idx], 1);
    }
    __syncthreads();

    for (int w = 0; w < 32; ++w)
        q[w][t] = cb[(size_t)sidx[w] * C_ + t];
    __syncthreads();

    float lsum = 0.f;
    const int w  = t & 31;
    const int cg = t >> 5;
    const size_t bb = (size_t)b * C_ * HW_ + h * 32 + w;
    for (int c = cg; c < C_; c += 8) {
        const size_t o = bb + (size_t)c * HW_;
        float qv = q[w][c];
        float zv = z[o];
        out_q[o] = qv;
        float dd = zv - qv;
        lsum = fmaf(dd, dd, lsum);
    }

    red[t] = lsum;
    __syncthreads();
    for (int s = 128; s > 0; s >>= 1) {
        if (t < s) red[t] += red[t + s];
        __syncthreads();
    }
    if (t == 0) g_partials[blockIdx.x] = red[0];
}

__global__ void __launch_bounds__(256) finalize_kernel(float* __restrict__ out) {
    __shared__ float red[256];
    const int t = threadIdx.x;

    float s = 0.f;
    for (int i = t; i < 512; i += 256) s += g_partials[i];
    red[t] = s;
    __syncthreads();
    for (int st = 128; st > 0; st >>= 1) {
        if (t < st) red[t] += red[t + st];
        __syncthreads();
    }
    if (t == 0) {
        float loss = red[0] / (float)NC_;
        out[OFF_LVQ] = loss;
        out[OFF_LC]  = loss;
    }
    __syncthreads();

    float e = 0.f;
    for (int k = t; k < K_; k += 256) {
        float p = (float)g_counts[k] * (1.f / (float)N_);
        if (p > 0.f) e += p * logf(p);
    }
    red[t] = e;
    __syncthreads();
    for (int st = 128; st > 0; st >>= 1) {
        if (t < st) red[t] += red[t + st];
        __syncthreads();
    }
    if (t == 0) out[OFF_P] = expf(-red[0]);
}

// ---------------------------------------------------------------------------
extern "C" void kernel_launch(void* const* d_in, const int* in_sizes, int n_in,
                              void* d_out, int out_size) {
    const float* z  = (const float*)d_in[0];
    const float* cb = (const float*)d_in[1];
    float* out = (float*)d_out;

    cudaFuncSetAttribute(mma_argmin_kernel,
                         cudaFuncAttributeMaxDynamicSharedMemorySize, SMEM_MAIN);

    zero_kernel<<<(K_ + 255) / 256, 256>>>();
    cn2_kernel<<<(K_ * 32) / 256, 256>>>(cb);
    splitA_kernel<<<NBLOCKS, 256>>>(z);
    splitB_kernel<<<QBLOCKS, 256>>>(cb);
    mma_argmin_kernel<<<NBLOCKS, 256, SMEM_MAIN>>>(out + OFF_IDX);
    rescue_kernel<<<N_, 256>>>(z, cb, out + OFF_IDX);
    gather_kernel<<<B_ * 32, 256>>>(z, cb, out + OFF_Q);
    finalize_kernel<<<1, 256>>>(out);
}